// round 12
// baseline (speedup 1.0000x reference)
#include <cuda_runtime.h>
#include <cuda_fp16.h>

#define N_NODES 100000
#define DIM     128
#define N_ANCH  4096
#define N_SAMP  512
// sim = dot_int / 127^2 ; arg = sim / TEMP = dot_int * (10 / 16129)
#define EXP_SCALE (10.0f / 16129.0f)

// Normalized feature table quantized to int8, 4 per int32:
// 100000 * 32 int32 = 12.8 MB (fits L2 easily). Row = 128B.
__device__ int g_xq[(size_t)N_NODES * (DIM / 4)];

// Kernel 1: warp per 2 rows -> L2-normalize, quantize to int8. Zero output.
__global__ void quantize_kernel(const float* __restrict__ x, float* __restrict__ out) {
    if (blockIdx.x == 0 && threadIdx.x == 0) out[0] = 0.0f;

    int pair = blockIdx.x * (blockDim.x >> 5) + (threadIdx.x >> 5);
    int row0 = pair * 2;
    if (row0 >= N_NODES) return;
    int lane = threadIdx.x & 31;
    bool has1 = (row0 + 1) < N_NODES;

    // Two independent row loads in flight.
    float4 v0 = reinterpret_cast<const float4*>(x + (size_t)row0 * DIM)[lane];
    float4 v1 = has1 ? reinterpret_cast<const float4*>(x + (size_t)(row0 + 1) * DIM)[lane]
                     : make_float4(1.f, 0.f, 0.f, 0.f);

    float s0 = v0.x * v0.x + v0.y * v0.y + v0.z * v0.z + v0.w * v0.w;
    float s1 = v1.x * v1.x + v1.y * v1.y + v1.z * v1.z + v1.w * v1.w;
    #pragma unroll
    for (int o = 16; o; o >>= 1) {
        s0 += __shfl_xor_sync(0xffffffffu, s0, o);
        s1 += __shfl_xor_sync(0xffffffffu, s1, o);
    }
    float inv0 = rsqrtf(s0) * 127.0f;
    float inv1 = rsqrtf(s1) * 127.0f;

    {
        int q0 = __float2int_rn(v0.x * inv0);
        int q1 = __float2int_rn(v0.y * inv0);
        int q2 = __float2int_rn(v0.z * inv0);
        int q3 = __float2int_rn(v0.w * inv0);
        unsigned p = (unsigned)(q0 & 0xff) | ((unsigned)(q1 & 0xff) << 8)
                   | ((unsigned)(q2 & 0xff) << 16) | ((unsigned)(q3 & 0xff) << 24);
        g_xq[(size_t)row0 * (DIM / 4) + lane] = (int)p;
    }
    if (has1) {
        int q0 = __float2int_rn(v1.x * inv1);
        int q1 = __float2int_rn(v1.y * inv1);
        int q2 = __float2int_rn(v1.z * inv1);
        int q3 = __float2int_rn(v1.w * inv1);
        unsigned p = (unsigned)(q0 & 0xff) | ((unsigned)(q1 & 0xff) << 8)
                   | ((unsigned)(q2 & 0xff) << 16) | ((unsigned)(q3 & 0xff) << 24);
        g_xq[(size_t)(row0 + 1) * (DIM / 4) + lane] = (int)p;
    }
}

// Kernel 2: one block per anchor, 16 warps, SINGLE PASS: each warp handles
// exactly 32 samples (no loop, no serial iteration dependency).
// Row layout: 8 lanes per row (int4/lane); 8 LDG.128 fetch 32 rows (MLP 8);
// 32 DP4A; packed select-fold (7 shuffles) transposes 32 dots so each lane
// owns one sample's exact int dot; epilogue once per sample.
__global__ __launch_bounds__(512, 2) void supcon_kernel(
    const int*   __restrict__ y,
    const int*   __restrict__ anchors,
    const int*   __restrict__ sampled,
    float*       __restrict__ out)
{
    const int a    = blockIdx.x;
    const int lane = threadIdx.x & 31;
    const int warp = threadIdx.x >> 5;
    const int grp  = lane >> 3;     // group 0..3
    const int gl   = lane & 7;      // lane within group (16B slice of the row)
    // Sample-within-group this lane will own after the packed fold.
    const int sig  = (((lane >> 2) & 1)) | (((lane >> 1) & 1) << 1) | ((lane & 1) << 2);

    __shared__ float s_num[16], s_den[16], s_cnt[16];

    const int anchor = anchors[a];
    const int ya     = y[anchor];

    const int4* xq4 = reinterpret_cast<const int4*>(g_xq);
    const int4  a4  = xq4[(size_t)anchor * 8 + gl];

    const int* samp = sampled + (size_t)a * N_SAMP;

    // This warp's 32 sample indices (coalesced) + prefetched owned label
    // (its L2 latency hides under the row gathers below).
    const int idx_lane = samp[warp * 32 + lane];
    const int my_idx   = __shfl_sync(0xffffffffu, idx_lane, sig * 4 + grp);
    const int my_y     = y[my_idx];

    // Row indices for the 8 rows this group covers.
    int rows[8];
    #pragma unroll
    for (int j = 0; j < 8; ++j)
        rows[j] = __shfl_sync(0xffffffffu, idx_lane, j * 4 + grp);

    // All 8 row loads in flight (one L2 round-trip).
    int4 sv[8];
    #pragma unroll
    for (int j = 0; j < 8; ++j)
        sv[j] = xq4[(size_t)rows[j] * 8 + gl];

    int d[8];
    #pragma unroll
    for (int j = 0; j < 8; ++j)
        d[j] = __dp4a(a4.x, sv[j].x,
               __dp4a(a4.y, sv[j].y,
               __dp4a(a4.z, sv[j].z,
               __dp4a(a4.w, sv[j].w, 0))));

    // Packed select-fold within each 8-lane group: 7 shuffles, exact int.
    int e4[4];
    #pragma unroll
    for (int j = 0; j < 4; ++j) {
        int t = (gl & 4) ? d[2*j] : d[2*j + 1];
        int r = __shfl_xor_sync(0xffffffffu, t, 4);
        e4[j] = ((gl & 4) ? d[2*j + 1] : d[2*j]) + r;
    }
    int f2[2];
    #pragma unroll
    for (int j = 0; j < 2; ++j) {
        int t = (gl & 2) ? e4[2*j] : e4[2*j + 1];
        int r = __shfl_xor_sync(0xffffffffu, t, 2);
        f2[j] = ((gl & 2) ? e4[2*j + 1] : e4[2*j]) + r;
    }
    int t1 = (gl & 1) ? f2[0] : f2[1];
    int r1 = __shfl_xor_sync(0xffffffffu, t1, 1);
    int g  = ((gl & 1) ? f2[1] : f2[0]) + r1;
    // g = full int dot of sample (warp*32 + sig*4 + grp); unique per lane.

    const float e = __expf(__int2float_rn(g) * EXP_SCALE);
    float den = e;
    float num = (my_y == ya) ? e : 0.0f;
    float cnt = (my_y == ya) ? 1.0f : 0.0f;

    // Warp reduce (each sample counted exactly once across the warp).
    #pragma unroll
    for (int o = 16; o; o >>= 1) {
        den += __shfl_xor_sync(0xffffffffu, den, o);
        num += __shfl_xor_sync(0xffffffffu, num, o);
        cnt += __shfl_xor_sync(0xffffffffu, cnt, o);
    }
    if (lane == 0) { s_num[warp] = num; s_den[warp] = den; s_cnt[warp] = cnt; }
    __syncthreads();

    if (threadIdx.x == 0) {
        float tn = 0.0f, td = 0.0f, tc = 0.0f;
        #pragma unroll
        for (int w = 0; w < 16; w++) { tn += s_num[w]; td += s_den[w]; tc += s_cnt[w]; }
        float loss = 0.0f;
        if (tc > 0.0f) loss = -logf(tn / td) / tc;
        atomicAdd(out, loss);
    }
}

extern "C" void kernel_launch(void* const* d_in, const int* in_sizes, int n_in,
                              void* d_out, int out_size) {
    const float* x       = (const float*)d_in[0];
    const int*   y       = (const int*)  d_in[1];
    const int*   anchors = (const int*)  d_in[2];
    const int*   sampled = (const int*)  d_in[3];
    float*       out     = (float*)d_out;

    const int wpb = 8;                       // warps per block, 2 rows each
    const int pairs = (N_NODES + 1) / 2;
    const int blocks = (pairs + wpb - 1) / wpb;
    quantize_kernel<<<blocks, wpb * 32>>>(x, out);

    supcon_kernel<<<N_ANCH, 512>>>(y, anchors, sampled, out);
}

// round 13
// speedup vs baseline: 1.2536x; 1.2536x over previous
#include <cuda_runtime.h>
#include <cuda_fp16.h>

#define N_NODES 100000
#define DIM     128
#define N_ANCH  4096
#define N_SAMP  512
// sim = dot_int / 127^2 ; arg = sim / TEMP = dot_int * (10 / 16129)
#define EXP_SCALE (10.0f / 16129.0f)

// Normalized feature table quantized to int8, 4 per int32:
// 100000 * 32 int32 = 12.8 MB (fits L2 easily). Row = 128B.
__device__ int g_xq[(size_t)N_NODES * (DIM / 4)];

// Kernel 1: warp per 2 rows -> L2-normalize, quantize to int8. Zero output.
// (R11 version: measured ~4.4us incl. overhead vs 8.9us for 1 row/warp.)
__global__ void quantize_kernel(const float* __restrict__ x, float* __restrict__ out) {
    if (blockIdx.x == 0 && threadIdx.x == 0) out[0] = 0.0f;

    int pair = blockIdx.x * (blockDim.x >> 5) + (threadIdx.x >> 5);
    int row0 = pair * 2;
    if (row0 >= N_NODES) return;
    int lane = threadIdx.x & 31;
    bool has1 = (row0 + 1) < N_NODES;

    // Two independent row loads in flight.
    float4 v0 = reinterpret_cast<const float4*>(x + (size_t)row0 * DIM)[lane];
    float4 v1 = has1 ? reinterpret_cast<const float4*>(x + (size_t)(row0 + 1) * DIM)[lane]
                     : make_float4(1.f, 0.f, 0.f, 0.f);

    float s0 = v0.x * v0.x + v0.y * v0.y + v0.z * v0.z + v0.w * v0.w;
    float s1 = v1.x * v1.x + v1.y * v1.y + v1.z * v1.z + v1.w * v1.w;
    #pragma unroll
    for (int o = 16; o; o >>= 1) {
        s0 += __shfl_xor_sync(0xffffffffu, s0, o);
        s1 += __shfl_xor_sync(0xffffffffu, s1, o);
    }
    float inv0 = rsqrtf(s0) * 127.0f;
    float inv1 = rsqrtf(s1) * 127.0f;

    {
        int q0 = __float2int_rn(v0.x * inv0);
        int q1 = __float2int_rn(v0.y * inv0);
        int q2 = __float2int_rn(v0.z * inv0);
        int q3 = __float2int_rn(v0.w * inv0);
        unsigned p = (unsigned)(q0 & 0xff) | ((unsigned)(q1 & 0xff) << 8)
                   | ((unsigned)(q2 & 0xff) << 16) | ((unsigned)(q3 & 0xff) << 24);
        g_xq[(size_t)row0 * (DIM / 4) + lane] = (int)p;
    }
    if (has1) {
        int q0 = __float2int_rn(v1.x * inv1);
        int q1 = __float2int_rn(v1.y * inv1);
        int q2 = __float2int_rn(v1.z * inv1);
        int q3 = __float2int_rn(v1.w * inv1);
        unsigned p = (unsigned)(q0 & 0xff) | ((unsigned)(q1 & 0xff) << 8)
                   | ((unsigned)(q2 & 0xff) << 16) | ((unsigned)(q3 & 0xff) << 24);
        g_xq[(size_t)(row0 + 1) * (DIM / 4) + lane] = (int)p;
    }
}

// Kernel 2: R9 version (measured 26.4us). One block per anchor, 8 warps,
// 32 samples per warp-iteration, 2 iterations with indices + labels hoisted
// and all 8 row LDG.128s per iteration in flight (MLP 8). Packed select-fold
// transposes 32 dots so each lane owns one sample's exact int dot.
__global__ __launch_bounds__(256, 4) void supcon_kernel(
    const int*   __restrict__ y,
    const int*   __restrict__ anchors,
    const int*   __restrict__ sampled,
    float*       __restrict__ out)
{
    const int a    = blockIdx.x;
    const int lane = threadIdx.x & 31;
    const int warp = threadIdx.x >> 5;
    const int grp  = lane >> 3;     // group 0..3
    const int gl   = lane & 7;      // lane within group (16B slice of the row)
    // Sample-within-group this lane will own after the packed fold.
    const int sig  = (((lane >> 2) & 1)) | (((lane >> 1) & 1) << 1) | ((lane & 1) << 2);

    __shared__ float s_num[8], s_den[8], s_cnt[8];

    const int anchor = anchors[a];
    const int ya     = y[anchor];

    const int4* xq4 = reinterpret_cast<const int4*>(g_xq);
    const int4  a4  = xq4[(size_t)anchor * 8 + gl];

    const int* samp = sampled + (size_t)a * N_SAMP;

    // Hoisted: both iterations' sample indices (coalesced) and prefetched
    // labels for the samples this lane will own (hidden under row gathers).
    const int idx_l0 = samp[warp * 32 + lane];
    const int idx_l1 = samp[256 + warp * 32 + lane];
    const int my_y0  = y[__shfl_sync(0xffffffffu, idx_l0, sig * 4 + grp)];
    const int my_y1  = y[__shfl_sync(0xffffffffu, idx_l1, sig * 4 + grp)];

    float num = 0.0f, den = 0.0f, cnt = 0.0f;

    #pragma unroll
    for (int it = 0; it < 2; ++it) {
        const int idx_lane = it ? idx_l1 : idx_l0;
        const int my_y     = it ? my_y1  : my_y0;

        // Row indices for all 8 rows this group covers.
        int rows[8];
        #pragma unroll
        for (int j = 0; j < 8; ++j)
            rows[j] = __shfl_sync(0xffffffffu, idx_lane, j * 4 + grp);

        // All 8 row loads in flight (one L2 round-trip).
        int4 sv[8];
        #pragma unroll
        for (int j = 0; j < 8; ++j)
            sv[j] = xq4[(size_t)rows[j] * 8 + gl];

        int d[8];
        #pragma unroll
        for (int j = 0; j < 8; ++j)
            d[j] = __dp4a(a4.x, sv[j].x,
                   __dp4a(a4.y, sv[j].y,
                   __dp4a(a4.z, sv[j].z,
                   __dp4a(a4.w, sv[j].w, 0))));

        // Packed select-fold within each 8-lane group: 7 shuffles, exact int.
        int e4[4];
        #pragma unroll
        for (int j = 0; j < 4; ++j) {
            int t = (gl & 4) ? d[2*j] : d[2*j + 1];
            int r = __shfl_xor_sync(0xffffffffu, t, 4);
            e4[j] = ((gl & 4) ? d[2*j + 1] : d[2*j]) + r;
        }
        int f2[2];
        #pragma unroll
        for (int j = 0; j < 2; ++j) {
            int t = (gl & 2) ? e4[2*j] : e4[2*j + 1];
            int r = __shfl_xor_sync(0xffffffffu, t, 2);
            f2[j] = ((gl & 2) ? e4[2*j + 1] : e4[2*j]) + r;
        }
        int t1 = (gl & 1) ? f2[0] : f2[1];
        int r1 = __shfl_xor_sync(0xffffffffu, t1, 1);
        int g  = ((gl & 1) ? f2[1] : f2[0]) + r1;
        // g = full int dot of sample (it*256 + warp*32 + sig*4 + grp).

        const float e = __expf(__int2float_rn(g) * EXP_SCALE);
        den += e;
        if (my_y == ya) { num += e; cnt += 1.0f; }
    }

    // Warp reduce (each sample counted exactly once across the warp).
    #pragma unroll
    for (int o = 16; o; o >>= 1) {
        den += __shfl_xor_sync(0xffffffffu, den, o);
        num += __shfl_xor_sync(0xffffffffu, num, o);
        cnt += __shfl_xor_sync(0xffffffffu, cnt, o);
    }
    if (lane == 0) { s_num[warp] = num; s_den[warp] = den; s_cnt[warp] = cnt; }
    __syncthreads();

    if (threadIdx.x == 0) {
        float tn = 0.0f, td = 0.0f, tc = 0.0f;
        #pragma unroll
        for (int w = 0; w < 8; w++) { tn += s_num[w]; td += s_den[w]; tc += s_cnt[w]; }
        float loss = 0.0f;
        if (tc > 0.0f) loss = -logf(tn / td) / tc;
        atomicAdd(out, loss);
    }
}

extern "C" void kernel_launch(void* const* d_in, const int* in_sizes, int n_in,
                              void* d_out, int out_size) {
    const float* x       = (const float*)d_in[0];
    const int*   y       = (const int*)  d_in[1];
    const int*   anchors = (const int*)  d_in[2];
    const int*   sampled = (const int*)  d_in[3];
    float*       out     = (float*)d_out;

    const int wpb = 8;                       // warps per block, 2 rows each
    const int pairs = (N_NODES + 1) / 2;
    const int blocks = (pairs + wpb - 1) / wpb;
    quantize_kernel<<<blocks, wpb * 32>>>(x, out);

    supcon_kernel<<<N_ANCH, 256>>>(y, anchors, sampled, out);
}

// round 14
// speedup vs baseline: 1.2809x; 1.0218x over previous
#include <cuda_runtime.h>
#include <cuda_fp16.h>

#define N_NODES 100000
#define DIM     128
#define N_ANCH  4096
#define N_SAMP  512
// sim = dot_int / 127^2 ; arg = sim / TEMP = dot_int * (10 / 16129)
#define EXP_SCALE (10.0f / 16129.0f)

// Normalized feature table quantized to int8, 4 per int32:
// 100000 * 32 int32 = 12.8 MB (fits L2 easily). Row = 128B.
__device__ int g_xq[(size_t)N_NODES * (DIM / 4)];

// Kernel 1: warp per 4 rows -> L2-normalize, quantize to int8. Zero output.
// 4 independent 512B row loads in flight per warp (latency-bound, L2-warm).
__global__ void quantize_kernel(const float* __restrict__ x, float* __restrict__ out) {
    if (blockIdx.x == 0 && threadIdx.x == 0) out[0] = 0.0f;

    int quad = blockIdx.x * (blockDim.x >> 5) + (threadIdx.x >> 5);
    int row0 = quad * 4;
    if (row0 >= N_NODES) return;
    int lane = threadIdx.x & 31;

    float4 v[4];
    #pragma unroll
    for (int j = 0; j < 4; ++j) {
        int row = row0 + j;
        v[j] = (row < N_NODES)
             ? reinterpret_cast<const float4*>(x + (size_t)row * DIM)[lane]
             : make_float4(1.f, 0.f, 0.f, 0.f);
    }

    float s[4];
    #pragma unroll
    for (int j = 0; j < 4; ++j)
        s[j] = v[j].x * v[j].x + v[j].y * v[j].y + v[j].z * v[j].z + v[j].w * v[j].w;
    #pragma unroll
    for (int o = 16; o; o >>= 1) {
        #pragma unroll
        for (int j = 0; j < 4; ++j)
            s[j] += __shfl_xor_sync(0xffffffffu, s[j], o);
    }

    #pragma unroll
    for (int j = 0; j < 4; ++j) {
        int row = row0 + j;
        if (row >= N_NODES) break;
        float inv = rsqrtf(s[j]) * 127.0f;
        int q0 = __float2int_rn(v[j].x * inv);
        int q1 = __float2int_rn(v[j].y * inv);
        int q2 = __float2int_rn(v[j].z * inv);
        int q3 = __float2int_rn(v[j].w * inv);
        unsigned p = (unsigned)(q0 & 0xff) | ((unsigned)(q1 & 0xff) << 8)
                   | ((unsigned)(q2 & 0xff) << 16) | ((unsigned)(q3 & 0xff) << 24);
        g_xq[(size_t)row * (DIM / 4) + lane] = (int)p;
    }
}

// Kernel 2: one block per anchor, 8 warps, 64 samples per warp in 2
// SOFTWARE-PIPELINED iterations: iteration 1's 8 row loads are issued right
// after iteration 0's dp4a (sv0 registers retired), so iteration 0's
// fold + exp tail runs UNDER iteration 1's L2 round-trip.
__global__ __launch_bounds__(256, 4) void supcon_kernel(
    const int*   __restrict__ y,
    const int*   __restrict__ anchors,
    const int*   __restrict__ sampled,
    float*       __restrict__ out)
{
    const int a    = blockIdx.x;
    const int lane = threadIdx.x & 31;
    const int warp = threadIdx.x >> 5;
    const int grp  = lane >> 3;     // group 0..3
    const int gl   = lane & 7;      // lane within group (16B slice of the row)
    // Sample-within-group this lane will own after the packed fold.
    const int sig  = (((lane >> 2) & 1)) | (((lane >> 1) & 1) << 1) | ((lane & 1) << 2);

    __shared__ float s_num[8], s_den[8], s_cnt[8];

    const int anchor = anchors[a];
    const int ya     = y[anchor];

    const int4* xq4 = reinterpret_cast<const int4*>(g_xq);
    const int4  a4  = xq4[(size_t)anchor * 8 + gl];

    const int* samp = sampled + (size_t)a * N_SAMP;

    // Hoisted: both iterations' sample indices + owned labels (prefetched;
    // their latency hides under the row gathers).
    const int idx_l0 = samp[warp * 32 + lane];
    const int idx_l1 = samp[256 + warp * 32 + lane];
    const int my_y0  = y[__shfl_sync(0xffffffffu, idx_l0, sig * 4 + grp)];
    const int my_y1  = y[__shfl_sync(0xffffffffu, idx_l1, sig * 4 + grp)];

    int rows0[8], rows1[8];
    #pragma unroll
    for (int j = 0; j < 8; ++j) {
        rows0[j] = __shfl_sync(0xffffffffu, idx_l0, j * 4 + grp);
        rows1[j] = __shfl_sync(0xffffffffu, idx_l1, j * 4 + grp);
    }

    // ---- iteration 0 loads (8 LDG.128 in flight) ----
    int4 sv0[8];
    #pragma unroll
    for (int j = 0; j < 8; ++j)
        sv0[j] = xq4[(size_t)rows0[j] * 8 + gl];

    // dp4a0: consumes sv0 (registers retire here).
    int d0[8];
    #pragma unroll
    for (int j = 0; j < 8; ++j)
        d0[j] = __dp4a(a4.x, sv0[j].x,
                __dp4a(a4.y, sv0[j].y,
                __dp4a(a4.z, sv0[j].z,
                __dp4a(a4.w, sv0[j].w, 0))));

    // ---- iteration 1 loads issued NOW: round-trip overlaps fold0/epi0 ----
    int4 sv1[8];
    #pragma unroll
    for (int j = 0; j < 8; ++j)
        sv1[j] = xq4[(size_t)rows1[j] * 8 + gl];

    float num, den, cnt;

    // fold0 + epilogue0 (runs under sv1's L2 latency)
    {
        int e4[4];
        #pragma unroll
        for (int j = 0; j < 4; ++j) {
            int t = (gl & 4) ? d0[2*j] : d0[2*j + 1];
            int r = __shfl_xor_sync(0xffffffffu, t, 4);
            e4[j] = ((gl & 4) ? d0[2*j + 1] : d0[2*j]) + r;
        }
        int f2[2];
        #pragma unroll
        for (int j = 0; j < 2; ++j) {
            int t = (gl & 2) ? e4[2*j] : e4[2*j + 1];
            int r = __shfl_xor_sync(0xffffffffu, t, 2);
            f2[j] = ((gl & 2) ? e4[2*j + 1] : e4[2*j]) + r;
        }
        int t1 = (gl & 1) ? f2[0] : f2[1];
        int r1 = __shfl_xor_sync(0xffffffffu, t1, 1);
        int g  = ((gl & 1) ? f2[1] : f2[0]) + r1;

        const float e = __expf(__int2float_rn(g) * EXP_SCALE);
        den = e;
        num = (my_y0 == ya) ? e : 0.0f;
        cnt = (my_y0 == ya) ? 1.0f : 0.0f;
    }

    // dp4a1 + fold1 + epilogue1
    {
        int d1[8];
        #pragma unroll
        for (int j = 0; j < 8; ++j)
            d1[j] = __dp4a(a4.x, sv1[j].x,
                    __dp4a(a4.y, sv1[j].y,
                    __dp4a(a4.z, sv1[j].z,
                    __dp4a(a4.w, sv1[j].w, 0))));

        int e4[4];
        #pragma unroll
        for (int j = 0; j < 4; ++j) {
            int t = (gl & 4) ? d1[2*j] : d1[2*j + 1];
            int r = __shfl_xor_sync(0xffffffffu, t, 4);
            e4[j] = ((gl & 4) ? d1[2*j + 1] : d1[2*j]) + r;
        }
        int f2[2];
        #pragma unroll
        for (int j = 0; j < 2; ++j) {
            int t = (gl & 2) ? e4[2*j] : e4[2*j + 1];
            int r = __shfl_xor_sync(0xffffffffu, t, 2);
            f2[j] = ((gl & 2) ? e4[2*j + 1] : e4[2*j]) + r;
        }
        int t1 = (gl & 1) ? f2[0] : f2[1];
        int r1 = __shfl_xor_sync(0xffffffffu, t1, 1);
        int g  = ((gl & 1) ? f2[1] : f2[0]) + r1;

        const float e = __expf(__int2float_rn(g) * EXP_SCALE);
        den += e;
        if (my_y1 == ya) { num += e; cnt += 1.0f; }
    }

    // Warp reduce (each sample counted exactly once across the warp).
    #pragma unroll
    for (int o = 16; o; o >>= 1) {
        den += __shfl_xor_sync(0xffffffffu, den, o);
        num += __shfl_xor_sync(0xffffffffu, num, o);
        cnt += __shfl_xor_sync(0xffffffffu, cnt, o);
    }
    if (lane == 0) { s_num[warp] = num; s_den[warp] = den; s_cnt[warp] = cnt; }
    __syncthreads();

    if (threadIdx.x == 0) {
        float tn = 0.0f, td = 0.0f, tc = 0.0f;
        #pragma unroll
        for (int w = 0; w < 8; w++) { tn += s_num[w]; td += s_den[w]; tc += s_cnt[w]; }
        float loss = 0.0f;
        if (tc > 0.0f) loss = -logf(tn / td) / tc;
        atomicAdd(out, loss);
    }
}

extern "C" void kernel_launch(void* const* d_in, const int* in_sizes, int n_in,
                              void* d_out, int out_size) {
    const float* x       = (const float*)d_in[0];
    const int*   y       = (const int*)  d_in[1];
    const int*   anchors = (const int*)  d_in[2];
    const int*   sampled = (const int*)  d_in[3];
    float*       out     = (float*)d_out;

    const int wpb = 8;                       // warps per block, 4 rows each
    const int quads = (N_NODES + 3) / 4;
    const int blocks = (quads + wpb - 1) / wpb;
    quantize_kernel<<<blocks, wpb * 32>>>(x, out);

    supcon_kernel<<<N_ANCH, 256>>>(y, anchors, sampled, out);
}

// round 15
// speedup vs baseline: 1.3268x; 1.0359x over previous
#include <cuda_runtime.h>
#include <cuda_fp16.h>

#define N_NODES 100000
#define DIM     128
#define N_ANCH  4096
#define N_SAMP  512
// sim = dot_int / 127^2 ; arg = sim / TEMP = dot_int * (10 / 16129)
#define EXP_SCALE (10.0f / 16129.0f)

// Normalized feature table quantized to int8, 4 per int32:
// 100000 * 32 int32 = 12.8 MB (fits L2 easily). Row = 128B.
__device__ int g_xq[(size_t)N_NODES * (DIM / 4)];

// Kernel 1: warp per 4 rows -> L2-normalize, quantize to int8. Zero output.
__global__ void quantize_kernel(const float* __restrict__ x, float* __restrict__ out) {
    if (blockIdx.x == 0 && threadIdx.x == 0) out[0] = 0.0f;

    int quad = blockIdx.x * (blockDim.x >> 5) + (threadIdx.x >> 5);
    int row0 = quad * 4;
    if (row0 >= N_NODES) return;
    int lane = threadIdx.x & 31;

    float4 v[4];
    #pragma unroll
    for (int j = 0; j < 4; ++j) {
        int row = row0 + j;
        v[j] = (row < N_NODES)
             ? reinterpret_cast<const float4*>(x + (size_t)row * DIM)[lane]
             : make_float4(1.f, 0.f, 0.f, 0.f);
    }

    float s[4];
    #pragma unroll
    for (int j = 0; j < 4; ++j)
        s[j] = v[j].x * v[j].x + v[j].y * v[j].y + v[j].z * v[j].z + v[j].w * v[j].w;
    #pragma unroll
    for (int o = 16; o; o >>= 1) {
        #pragma unroll
        for (int j = 0; j < 4; ++j)
            s[j] += __shfl_xor_sync(0xffffffffu, s[j], o);
    }

    #pragma unroll
    for (int j = 0; j < 4; ++j) {
        int row = row0 + j;
        if (row >= N_NODES) break;
        float inv = rsqrtf(s[j]) * 127.0f;
        int q0 = __float2int_rn(v[j].x * inv);
        int q1 = __float2int_rn(v[j].y * inv);
        int q2 = __float2int_rn(v[j].z * inv);
        int q3 = __float2int_rn(v[j].w * inv);
        unsigned p = (unsigned)(q0 & 0xff) | ((unsigned)(q1 & 0xff) << 8)
                   | ((unsigned)(q2 & 0xff) << 16) | ((unsigned)(q3 & 0xff) << 24);
        g_xq[(size_t)row * (DIM / 4) + lane] = (int)p;
    }
}

// Kernel 2: one block per anchor, 8 warps, 2 iterations of 32 samples.
// Register-lean: row indices are shuffled LAZILY inside each iteration from
// the 1-reg idx_lane (not pre-expanded), so peak live regs during the
// 8-LDG.128 load phase fit a 51-reg / 5-blocks-per-SM occupancy budget.
__global__ __launch_bounds__(256, 5) void supcon_kernel(
    const int*   __restrict__ y,
    const int*   __restrict__ anchors,
    const int*   __restrict__ sampled,
    float*       __restrict__ out)
{
    const int a    = blockIdx.x;
    const int lane = threadIdx.x & 31;
    const int warp = threadIdx.x >> 5;
    const int grp  = lane >> 3;     // group 0..3
    const int gl   = lane & 7;      // lane within group (16B slice of the row)
    // Sample-within-group this lane will own after the packed fold.
    const int sig  = (((lane >> 2) & 1)) | (((lane >> 1) & 1) << 1) | ((lane & 1) << 2);

    __shared__ float s_num[8], s_den[8], s_cnt[8];

    const int anchor = anchors[a];
    const int ya     = y[anchor];

    const int4* xq4 = reinterpret_cast<const int4*>(g_xq);
    const int4  a4  = xq4[(size_t)anchor * 8 + gl];

    const int* samp = sampled + (size_t)a * N_SAMP;

    // Hoisted: both iterations' sample indices (1 reg each) + owned labels
    // (prefetched; latency hides under the row gathers).
    const int idx_l0 = samp[warp * 32 + lane];
    const int idx_l1 = samp[256 + warp * 32 + lane];
    const int my_y0  = y[__shfl_sync(0xffffffffu, idx_l0, sig * 4 + grp)];
    const int my_y1  = y[__shfl_sync(0xffffffffu, idx_l1, sig * 4 + grp)];

    float num = 0.0f, den = 0.0f, cnt = 0.0f;

    #pragma unroll
    for (int it = 0; it < 2; ++it) {
        const int idx_lane = it ? idx_l1 : idx_l0;
        const int my_y     = it ? my_y1  : my_y0;

        // All 8 row loads in flight; addresses consumed immediately so the
        // shuffled indices don't stay live.
        int4 sv[8];
        #pragma unroll
        for (int j = 0; j < 8; ++j) {
            int row = __shfl_sync(0xffffffffu, idx_lane, j * 4 + grp);
            sv[j] = xq4[(size_t)row * 8 + gl];
        }

        int d[8];
        #pragma unroll
        for (int j = 0; j < 8; ++j)
            d[j] = __dp4a(a4.x, sv[j].x,
                   __dp4a(a4.y, sv[j].y,
                   __dp4a(a4.z, sv[j].z,
                   __dp4a(a4.w, sv[j].w, 0))));

        // Packed select-fold within each 8-lane group: 7 shuffles, exact int.
        int e4[4];
        #pragma unroll
        for (int j = 0; j < 4; ++j) {
            int t = (gl & 4) ? d[2*j] : d[2*j + 1];
            int r = __shfl_xor_sync(0xffffffffu, t, 4);
            e4[j] = ((gl & 4) ? d[2*j + 1] : d[2*j]) + r;
        }
        int f2[2];
        #pragma unroll
        for (int j = 0; j < 2; ++j) {
            int t = (gl & 2) ? e4[2*j] : e4[2*j + 1];
            int r = __shfl_xor_sync(0xffffffffu, t, 2);
            f2[j] = ((gl & 2) ? e4[2*j + 1] : e4[2*j]) + r;
        }
        int t1 = (gl & 1) ? f2[0] : f2[1];
        int r1 = __shfl_xor_sync(0xffffffffu, t1, 1);
        int g  = ((gl & 1) ? f2[1] : f2[0]) + r1;
        // g = full int dot of sample (it*256 + warp*32 + sig*4 + grp).

        const float e = __expf(__int2float_rn(g) * EXP_SCALE);
        den += e;
        if (my_y == ya) { num += e; cnt += 1.0f; }
    }

    // Warp reduce (each sample counted exactly once across the warp).
    #pragma unroll
    for (int o = 16; o; o >>= 1) {
        den += __shfl_xor_sync(0xffffffffu, den, o);
        num += __shfl_xor_sync(0xffffffffu, num, o);
        cnt += __shfl_xor_sync(0xffffffffu, cnt, o);
    }
    if (lane == 0) { s_num[warp] = num; s_den[warp] = den; s_cnt[warp] = cnt; }
    __syncthreads();

    if (threadIdx.x == 0) {
        float tn = 0.0f, td = 0.0f, tc = 0.0f;
        #pragma unroll
        for (int w = 0; w < 8; w++) { tn += s_num[w]; td += s_den[w]; tc += s_cnt[w]; }
        float loss = 0.0f;
        if (tc > 0.0f) loss = -logf(tn / td) / tc;
        atomicAdd(out, loss);
    }
}

extern "C" void kernel_launch(void* const* d_in, const int* in_sizes, int n_in,
                              void* d_out, int out_size) {
    const float* x       = (const float*)d_in[0];
    const int*   y       = (const int*)  d_in[1];
    const int*   anchors = (const int*)  d_in[2];
    const int*   sampled = (const int*)  d_in[3];
    float*       out     = (float*)d_out;

    const int wpb = 8;                       // warps per block, 4 rows each
    const int quads = (N_NODES + 3) / 4;
    const int blocks = (quads + wpb - 1) / wpb;
    quantize_kernel<<<blocks, wpb * 32>>>(x, out);

    supcon_kernel<<<N_ANCH, 256>>>(y, anchors, sampled, out);
}